// round 5
// baseline (speedup 1.0000x reference)
#include <cuda_runtime.h>
#include <math.h>

#define TKN 8192
#define DIM 1024
#define HID 2048
#define NE  16

// ---------------- scratch (no allocation allowed) ----------------
__device__ float g_exps[TKN * NE];     // exp(logits) (unnormalized dispatch numerator)
__device__ float g_comb[TKN * NE];     // combine = row softmax
__device__ float g_colsum[NE];         // sum_t exp(logits[t,e])
__device__ float g_usage[NE];          // sum_t combine[t,e]
__device__ float g_ent;                // sum_t entropy_t
__device__ float g_slots[NE * DIM];    // dispatch^T @ x
__device__ float g_hbuf[NE * HID];     // fc1 out -> LN+GELU in place
__device__ float g_sout[NE * DIM];     // fc2 out

// ---------------- kernel 0: zero accumulators ----------------
__global__ void k_init() {
    int i = blockIdx.x * blockDim.x + threadIdx.x;
    if (i < NE) { g_colsum[i] = 0.f; g_usage[i] = 0.f; }
    if (i == 0) g_ent = 0.f;
    if (i < NE * DIM) g_slots[i] = 0.f;
}

// ---------------- kernel 1: logits + both softmaxes + stats ----------------
// 256 blocks x 256 threads; 8 warps/block, 4 tokens per warp.
// router_w (64KB) in dynamic shared (float4).
__global__ void __launch_bounds__(256) k_router(const float* __restrict__ x,
                                                const float* __restrict__ rw) {
    extern __shared__ float4 rwsh[];          // 16 * 256 float4 = 64 KB
    __shared__ float s_col[NE];
    __shared__ float s_use[NE];
    __shared__ float s_ent;
    const int tid = threadIdx.x;

    const float4* rw4 = reinterpret_cast<const float4*>(rw);
#pragma unroll
    for (int i = 0; i < 16; i++) rwsh[tid + i * 256] = rw4[tid + i * 256];
    if (tid < NE) { s_col[tid] = 0.f; s_use[tid] = 0.f; }
    if (tid == 0) s_ent = 0.f;
    __syncthreads();

    const int warp = tid >> 5, lane = tid & 31;
    const int t0 = blockIdx.x * 32 + warp * 4;

    float acc[NE][4];
#pragma unroll
    for (int e = 0; e < NE; e++)
#pragma unroll
        for (int j = 0; j < 4; j++) acc[e][j] = 0.f;

    const float4* x4 = reinterpret_cast<const float4*>(x);
#pragma unroll
    for (int k = 0; k < 8; k++) {
        float4 xv[4];
#pragma unroll
        for (int j = 0; j < 4; j++)
            xv[j] = x4[(size_t)(t0 + j) * 256 + k * 32 + lane];
#pragma unroll
        for (int e = 0; e < NE; e++) {
            float4 r = rwsh[e * 256 + k * 32 + lane];
#pragma unroll
            for (int j = 0; j < 4; j++) {
                acc[e][j] = fmaf(xv[j].x, r.x, acc[e][j]);
                acc[e][j] = fmaf(xv[j].y, r.y, acc[e][j]);
                acc[e][j] = fmaf(xv[j].z, r.z, acc[e][j]);
                acc[e][j] = fmaf(xv[j].w, r.w, acc[e][j]);
            }
        }
    }
    // full 32-lane butterfly: every lane ends with all 64 sums
#pragma unroll
    for (int e = 0; e < NE; e++)
#pragma unroll
        for (int j = 0; j < 4; j++)
#pragma unroll
            for (int m = 16; m > 0; m >>= 1)
                acc[e][j] += __shfl_xor_sync(0xffffffffu, acc[e][j], m);

    const int e = lane & 15;   // lanes 16..31 mirror lanes 0..15
#pragma unroll
    for (int j = 0; j < 4; j++) {
        float l = acc[e][j];                       // logit (TEMP=1)
        float mx = l;
#pragma unroll
        for (int msk = 8; msk; msk >>= 1)
            mx = fmaxf(mx, __shfl_xor_sync(0xffffffffu, mx, msk));
        float ex  = expf(l - mx);
        float den = ex;
#pragma unroll
        for (int msk = 8; msk; msk >>= 1)
            den += __shfl_xor_sync(0xffffffffu, den, msk);
        float comb = ex / den;                     // row softmax (combine)
        float raw  = ex * expf(mx);                // = exp(l), dispatch numerator
        float ec   = -comb * logf(comb + 1e-8f);
#pragma unroll
        for (int msk = 8; msk; msk >>= 1)
            ec += __shfl_xor_sync(0xffffffffu, ec, msk);

        const int t = t0 + j;
        if (lane < 16) {
            g_exps[t * NE + e] = raw;
            g_comb[t * NE + e] = comb;
            atomicAdd(&s_col[e], raw);
            atomicAdd(&s_use[e], comb);
        }
        if (lane == 0) atomicAdd(&s_ent, ec);
    }
    __syncthreads();
    if (tid < NE) {
        atomicAdd(&g_colsum[tid], s_col[tid]);
        atomicAdd(&g_usage[tid],  s_use[tid]);
    }
    if (tid == 0) atomicAdd(&g_ent, s_ent);
}

// ---------------- kernel 2: slots = dispatch^T @ x ----------------
// grid (DIM/256, TKN/128). Block: 256 d-columns (1 thread each) x 128 tokens.
__global__ void __launch_bounds__(256) k_slots(const float* __restrict__ x) {
    __shared__ float4 wts[128 * 4];   // per-token dispatch weights, 16 experts as 4 float4
    __shared__ float  inv[NE];
    const int tid = threadIdx.x;
    if (tid < NE) inv[tid] = 1.0f / g_colsum[tid];
    __syncthreads();

    const int tbase = blockIdx.y * 128;
    if (tid < 128) {
        const float4* ge = reinterpret_cast<const float4*>(g_exps) + (size_t)(tbase + tid) * 4;
        float4 a = ge[0], b = ge[1], c = ge[2], d4 = ge[3];
        a.x *= inv[0];  a.y *= inv[1];  a.z *= inv[2];  a.w *= inv[3];
        b.x *= inv[4];  b.y *= inv[5];  b.z *= inv[6];  b.w *= inv[7];
        c.x *= inv[8];  c.y *= inv[9];  c.z *= inv[10]; c.w *= inv[11];
        d4.x *= inv[12]; d4.y *= inv[13]; d4.z *= inv[14]; d4.w *= inv[15];
        wts[tid * 4 + 0] = a; wts[tid * 4 + 1] = b;
        wts[tid * 4 + 2] = c; wts[tid * 4 + 3] = d4;
    }
    __syncthreads();

    const int d = blockIdx.x * 256 + tid;
    const float* xp = x + (size_t)tbase * DIM + d;
    float acc[NE];
#pragma unroll
    for (int e = 0; e < NE; e++) acc[e] = 0.f;

    for (int tt = 0; tt < 128; tt += 8) {
        float xv[8];
#pragma unroll
        for (int u = 0; u < 8; u++) xv[u] = xp[(size_t)(tt + u) * DIM];
#pragma unroll
        for (int u = 0; u < 8; u++) {
            const float4 A  = wts[(tt + u) * 4 + 0];
            const float4 B  = wts[(tt + u) * 4 + 1];
            const float4 C  = wts[(tt + u) * 4 + 2];
            const float4 Dv = wts[(tt + u) * 4 + 3];
            acc[0]  = fmaf(A.x,  xv[u], acc[0]);  acc[1]  = fmaf(A.y,  xv[u], acc[1]);
            acc[2]  = fmaf(A.z,  xv[u], acc[2]);  acc[3]  = fmaf(A.w,  xv[u], acc[3]);
            acc[4]  = fmaf(B.x,  xv[u], acc[4]);  acc[5]  = fmaf(B.y,  xv[u], acc[5]);
            acc[6]  = fmaf(B.z,  xv[u], acc[6]);  acc[7]  = fmaf(B.w,  xv[u], acc[7]);
            acc[8]  = fmaf(C.x,  xv[u], acc[8]);  acc[9]  = fmaf(C.y,  xv[u], acc[9]);
            acc[10] = fmaf(C.z,  xv[u], acc[10]); acc[11] = fmaf(C.w,  xv[u], acc[11]);
            acc[12] = fmaf(Dv.x, xv[u], acc[12]); acc[13] = fmaf(Dv.y, xv[u], acc[13]);
            acc[14] = fmaf(Dv.z, xv[u], acc[14]); acc[15] = fmaf(Dv.w, xv[u], acc[15]);
        }
    }
#pragma unroll
    for (int e = 0; e < NE; e++) atomicAdd(&g_slots[e * DIM + d], acc[e]);
}

// ---------------- kernel 3: h = slots @ w1^T (+b1). One warp per (e,h) ----------------
__global__ void __launch_bounds__(256) k_fc1(const float* __restrict__ w1,
                                             const float* __restrict__ b1) {
    const int gw = blockIdx.x * 8 + (threadIdx.x >> 5);  // 0..32767
    const int lane = threadIdx.x & 31;
    const int e = gw >> 11;                              // /HID
    const float4* wr = reinterpret_cast<const float4*>(w1) + (size_t)gw * 256;
    const float4* sr = reinterpret_cast<const float4*>(g_slots) + e * 256;
    float acc = 0.f;
#pragma unroll
    for (int k = 0; k < 8; k++) {
        float4 w = wr[k * 32 + lane];
        float4 s = sr[k * 32 + lane];
        acc += w.x * s.x + w.y * s.y + w.z * s.z + w.w * s.w;
    }
#pragma unroll
    for (int m = 16; m > 0; m >>= 1)
        acc += __shfl_xor_sync(0xffffffffu, acc, m);
    if (lane == 0) g_hbuf[gw] = acc + b1[gw];
}

// ---------------- kernel 4: LayerNorm + exact GELU, plus scalar outputs ----------------
__global__ void __launch_bounds__(256) k_ln_gelu(const float* __restrict__ ln_g,
                                                 const float* __restrict__ ln_b,
                                                 const float* __restrict__ rw,
                                                 float* __restrict__ out, int out_size) {
    __shared__ float red[256];
    const int tid = threadIdx.x;

    if (blockIdx.x == NE) {   // scalars: router_loss + entropy
        __shared__ float smean[NE];
        for (int e = 0; e < NE; e++) {
            float s = 0.f;
            for (int i = tid; i < DIM; i += 256) s += rw[e * DIM + i];
            red[tid] = s; __syncthreads();
            for (int st = 128; st; st >>= 1) {
                if (tid < st) red[tid] += red[tid + st];
                __syncthreads();
            }
            if (tid == 0) smean[e] = red[0] * (1.f / DIM);
            __syncthreads();
        }
        if (tid == 0) {
            float m = -1e30f;
            for (int e2 = 0; e2 < NE; e2++) m = fmaxf(m, smean[e2]);
            float den = 0.f, pe[NE];
            for (int e2 = 0; e2 < NE; e2++) { pe[e2] = expf(smean[e2] - m); den += pe[e2]; }
            float loss = 0.f;
            for (int e2 = 0; e2 < NE; e2++)
                loss += (g_usage[e2] * (1.f / TKN)) * (pe[e2] / den);
            loss *= (float)NE;
            if (out_size > TKN * DIM)     out[TKN * DIM]     = loss;
            if (out_size > TKN * DIM + 1) out[TKN * DIM + 1] = g_ent * (1.f / TKN);
        }
        return;
    }

    const int e = blockIdx.x;
    float v[8]; float s = 0.f;
#pragma unroll
    for (int i = 0; i < 8; i++) { v[i] = g_hbuf[e * HID + tid + i * 256]; s += v[i]; }
    red[tid] = s; __syncthreads();
    for (int st = 128; st; st >>= 1) {
        if (tid < st) red[tid] += red[tid + st];
        __syncthreads();
    }
    const float mu = red[0] * (1.f / HID);
    __syncthreads();
    float s2 = 0.f;
#pragma unroll
    for (int i = 0; i < 8; i++) { float dv = v[i] - mu; s2 += dv * dv; }
    red[tid] = s2; __syncthreads();
    for (int st = 128; st; st >>= 1) {
        if (tid < st) red[tid] += red[tid + st];
        __syncthreads();
    }
    const float rstd = rsqrtf(red[0] * (1.f / HID) + 1e-5f);
#pragma unroll
    for (int i = 0; i < 8; i++) {
        int idx = e * HID + tid + i * 256;
        float hv = (v[i] - mu) * rstd * ln_g[idx] + ln_b[idx];
        g_hbuf[idx] = hv * 0.5f * (1.f + erff(hv * 0.70710678118654752f));
    }
}

// ---------------- kernel 5: slot_out = h @ w2^T (+b2). One warp per (e,d) ----------------
__global__ void __launch_bounds__(256) k_fc2(const float* __restrict__ w2,
                                             const float* __restrict__ b2) {
    const int gw = blockIdx.x * 8 + (threadIdx.x >> 5);  // 0..16383
    const int lane = threadIdx.x & 31;
    const int e = gw >> 10;                              // /DIM
    const float4* wr = reinterpret_cast<const float4*>(w2) + (size_t)gw * 512;
    const float4* hr = reinterpret_cast<const float4*>(g_hbuf) + e * 512;
    float acc = 0.f;
#pragma unroll
    for (int k = 0; k < 16; k++) {
        float4 w = wr[k * 32 + lane];
        float4 h = hr[k * 32 + lane];
        acc += w.x * h.x + w.y * h.y + w.z * h.z + w.w * h.w;
    }
#pragma unroll
    for (int m = 16; m > 0; m >>= 1)
        acc += __shfl_xor_sync(0xffffffffu, acc, m);
    if (lane == 0) g_sout[gw] = acc + b2[gw];
}

// ---------------- kernel 6: out = combine @ slot_out ----------------
// 1024 blocks x 256 threads; 8 tokens/block; thread owns one float4 column group.
__global__ void __launch_bounds__(256) k_out(float* __restrict__ out) {
    __shared__ float comb[8 * NE];
    const int tid = threadIdx.x;
    const int tbase = blockIdx.x * 8;
    if (tid < 128) comb[tid] = g_comb[tbase * NE + tid];
    __syncthreads();

    const float4* so = reinterpret_cast<const float4*>(g_sout);
    float4 acc[8];
#pragma unroll
    for (int j = 0; j < 8; j++) acc[j] = make_float4(0.f, 0.f, 0.f, 0.f);
#pragma unroll
    for (int e = 0; e < NE; e++) {
        float4 s = so[e * 256 + tid];
#pragma unroll
        for (int j = 0; j < 8; j++) {
            float c = comb[j * NE + e];
            acc[j].x = fmaf(c, s.x, acc[j].x);
            acc[j].y = fmaf(c, s.y, acc[j].y);
            acc[j].z = fmaf(c, s.z, acc[j].z);
            acc[j].w = fmaf(c, s.w, acc[j].w);
        }
    }
    float4* o4 = reinterpret_cast<float4*>(out);
#pragma unroll
    for (int j = 0; j < 8; j++)
        o4[(size_t)(tbase + j) * 256 + tid] = acc[j];
}

// ---------------- launch ----------------
extern "C" void kernel_launch(void* const* d_in, const int* in_sizes, int n_in,
                              void* d_out, int out_size) {
    const float* x    = (const float*)d_in[0];
    const float* rw   = (const float*)d_in[1];
    const float* w1   = (const float*)d_in[2];
    const float* b1   = (const float*)d_in[3];
    const float* ln_g = (const float*)d_in[4];
    const float* ln_b = (const float*)d_in[5];
    const float* w2   = (const float*)d_in[6];
    const float* b2   = (const float*)d_in[7];
    float* out = (float*)d_out;

    cudaFuncSetAttribute((const void*)k_router,
                         cudaFuncAttributeMaxDynamicSharedMemorySize, 65536);

    k_init<<<64, 256>>>();
    k_router<<<TKN / 32, 256, 65536>>>(x, rw);
    k_slots<<<dim3(DIM / 256, TKN / 128), 256>>>(x);
    k_fc1<<<(NE * HID) / 8, 256>>>(w1, b1);
    k_ln_gelu<<<NE + 1, 256>>>(ln_g, ln_b, rw, out, out_size);
    k_fc2<<<(NE * DIM) / 8, 256>>>(w2, b2);
    k_out<<<TKN / 8, 256>>>(out);
}